// round 11
// baseline (speedup 1.0000x reference)
#include <cuda_runtime.h>
#include <cuda_bf16.h>
#include <cstdint>

#define N_NODES 50000
#define N_EDGES 1600000
#define FEAT    48
#define NUM_RELS 8

// ---------------------------------------------------------------------------
// Scratch (__device__ globals — no allocations).
// ---------------------------------------------------------------------------
__device__ float g_h1[(size_t)N_NODES * NUM_RELS * FEAT];   // 76.8 MB
__device__ float g_h2[(size_t)N_NODES * NUM_RELS * FEAT];   // 76.8 MB
__device__ int   g_cnt[N_NODES];
__device__ int   g_off[N_NODES + 1];
__device__ int   g_cur[N_NODES];
__device__ int2  g_meta[N_EDGES];                            // 12.8 MB
__device__ int   g_src_is64;

// ---------------------------------------------------------------------------
// Packed f32x2 helpers (Blackwell) — only reachable via PTX.
// ---------------------------------------------------------------------------
__device__ __forceinline__ unsigned long long pack2(float lo, float hi) {
    unsigned long long r;
    asm("mov.b64 %0, {%1, %2};" : "=l"(r) : "f"(lo), "f"(hi));
    return r;
}
__device__ __forceinline__ void unpack2(float& lo, float& hi, unsigned long long v) {
    asm("mov.b64 {%0, %1}, %2;" : "=f"(lo), "=f"(hi) : "l"(v));
}
#define FMA2(d, a, b) \
    asm("fma.rn.f32x2 %0, %1, %2, %0;" : "+l"(d) : "l"(a), "l"(b))

// ---------------------------------------------------------------------------
// K1 (launch #1): zero counts + src dtype detection (block 0).
// ---------------------------------------------------------------------------
__global__ void zero_detect_kernel(const int* __restrict__ src) {
    int i = blockIdx.x * 256 + threadIdx.x;
    if (i < N_NODES) g_cnt[i] = 0;
    if (blockIdx.x == 0) {
        __shared__ int s_any;
        if (threadIdx.x == 0) s_any = 0;
        __syncthreads();
        unsigned v = (unsigned)src[2 * threadIdx.x + 1];
        unsigned any = __ballot_sync(0xFFFFFFFFu, v != 0u);
        if ((threadIdx.x & 31) == 0 && any) atomicOr(&s_any, 1);
        __syncthreads();
        if (threadIdx.x == 0) g_src_is64 = (s_any == 0) ? 1 : 0;
    }
}

// ---------------------------------------------------------------------------
// K2 (launch #2): dst histogram, int4-vectorized.
// ---------------------------------------------------------------------------
__global__ __launch_bounds__(256)
void hist_kernel(const int4* __restrict__ dst4) {
    int i = blockIdx.x * 256 + threadIdx.x;
    if (i < N_EDGES / 4) {
        int4 d = dst4[i];
        atomicAdd(&g_cnt[d.x], 1);
        atomicAdd(&g_cnt[d.y], 1);
        atomicAdd(&g_cnt[d.z], 1);
        atomicAdd(&g_cnt[d.w], 1);
    }
}

// ---------------------------------------------------------------------------
// K3 (launch #3): single-block exclusive scan g_cnt -> g_off, g_cur.
// ---------------------------------------------------------------------------
__global__ __launch_bounds__(1024)
void scan_kernel() {
    __shared__ int partial[1024];
    const int t = threadIdx.x;
    const int CH = (N_NODES + 1023) / 1024;  // 49
    const int base = t * CH;

    int s = 0;
    for (int i = 0; i < CH; i++) {
        int idx = base + i;
        if (idx < N_NODES) s += g_cnt[idx];
    }
    partial[t] = s;
    __syncthreads();
    for (int o = 1; o < 1024; o <<= 1) {
        int v = (t >= o) ? partial[t - o] : 0;
        __syncthreads();
        partial[t] += v;
        __syncthreads();
    }
    int run = (t == 0) ? 0 : partial[t - 1];
    for (int i = 0; i < CH; i++) {
        int idx = base + i;
        if (idx < N_NODES) {
            g_off[idx] = run;
            g_cur[idx] = run;
            run += g_cnt[idx];
        }
    }
    if (t == 1023) g_off[N_NODES] = partial[1023];
}

// ---------------------------------------------------------------------------
// GEMM stage kernels. Layout per 128-thread block (one relation, 128 nodes):
//   jh   = tid>>6  (uniform per warp!)  -> output cols [jh*24, jh*24+24)
//   slot = tid&63 ; nodes n0 = base+slot, n1 = n0+64
// Per thread: 2 nodes x 24 outputs = 24 ull f32x2 accumulators (48 regs).
// Per u-step: 6 broadcast LDS.128 vs 24 FMA2 -> fma binds 2x over LSU.
// ~80 regs -> launch_bounds(128,5) -> up to 20 warps/SM (vs 8 in R7).
// ---------------------------------------------------------------------------

// K4 (launch #4 — PROFILED): stage 1, h1 = relu(X @ W1[r] + b1)
__global__ __launch_bounds__(128, 5)
void stage1_kernel(const float* __restrict__ X,
                   const float* __restrict__ W1,
                   const float* __restrict__ b1) {
    __shared__ __align__(16) float Ws[FEAT * FEAT];
    __shared__ float bs[FEAT];

    const int r   = blockIdx.y;
    const int tid = threadIdx.x;

    const float* wg = W1 + (size_t)r * FEAT * FEAT;
    for (int k = tid; k < FEAT * FEAT; k += 128) Ws[k] = wg[k];
    if (tid < FEAT) bs[tid] = b1[tid];
    __syncthreads();

    const int jh    = tid >> 6;
    const int slot  = tid & 63;
    const int jbase = jh * 24;
    const int n0 = blockIdx.x * 128 + slot;
    const int n1 = n0 + 64;
    const bool v0 = (n0 < N_NODES);
    const bool v1 = (n1 < N_NODES);
    const int c0 = v0 ? n0 : 0;
    const int c1 = v1 ? n1 : 0;

    unsigned long long accA[12], accB[12];
#pragma unroll
    for (int k = 0; k < 12; k++) {
        unsigned long long b = pack2(bs[jbase + 2 * k], bs[jbase + 2 * k + 1]);
        accA[k] = b;
        accB[k] = b;
    }

    const float4* xa4 = reinterpret_cast<const float4*>(X + (size_t)c0 * FEAT);
    const float4* xb4 = reinterpret_cast<const float4*>(X + (size_t)c1 * FEAT);
#pragma unroll
    for (int i4 = 0; i4 < FEAT / 4; i4++) {
        float4 xa = xa4[i4];
        float4 xb = xb4[i4];
#pragma unroll
        for (int u = 0; u < 4; u++) {
            float ai = (u == 0) ? xa.x : (u == 1) ? xa.y : (u == 2) ? xa.z : xa.w;
            float bi = (u == 0) ? xb.x : (u == 1) ? xb.y : (u == 2) ? xb.z : xb.w;
            unsigned long long a2 = pack2(ai, ai);
            unsigned long long b2 = pack2(bi, bi);
            const ulonglong2* w = reinterpret_cast<const ulonglong2*>(
                Ws + (i4 * 4 + u) * FEAT + jbase);
#pragma unroll
            for (int k = 0; k < 6; k++) {
                ulonglong2 wv = w[k];
                FMA2(accA[2 * k],     a2, wv.x);
                FMA2(accA[2 * k + 1], a2, wv.y);
                FMA2(accB[2 * k],     b2, wv.x);
                FMA2(accB[2 * k + 1], b2, wv.y);
            }
        }
    }

    if (v0) {
        ulonglong2* orow = reinterpret_cast<ulonglong2*>(
            g_h1 + ((size_t)n0 * NUM_RELS + r) * FEAT + jbase);
#pragma unroll
        for (int k = 0; k < 6; k++) {
            float x0, x1, x2, x3;
            unpack2(x0, x1, accA[2 * k]);
            unpack2(x2, x3, accA[2 * k + 1]);
            ulonglong2 o;
            o.x = pack2(fmaxf(x0, 0.f), fmaxf(x1, 0.f));
            o.y = pack2(fmaxf(x2, 0.f), fmaxf(x3, 0.f));
            orow[k] = o;
        }
    }
    if (v1) {
        ulonglong2* orow = reinterpret_cast<ulonglong2*>(
            g_h1 + ((size_t)n1 * NUM_RELS + r) * FEAT + jbase);
#pragma unroll
        for (int k = 0; k < 6; k++) {
            float x0, x1, x2, x3;
            unpack2(x0, x1, accB[2 * k]);
            unpack2(x2, x3, accB[2 * k + 1]);
            ulonglong2 o;
            o.x = pack2(fmaxf(x0, 0.f), fmaxf(x1, 0.f));
            o.y = pack2(fmaxf(x2, 0.f), fmaxf(x3, 0.f));
            orow[k] = o;
        }
    }
}

// K5 (launch #5): stage 2, h2 = h1 @ W2[r]
__global__ __launch_bounds__(128, 5)
void stage2_kernel(const float* __restrict__ W2) {
    __shared__ __align__(16) float Ws[FEAT * FEAT];

    const int r   = blockIdx.y;
    const int tid = threadIdx.x;

    const float* wg = W2 + (size_t)r * FEAT * FEAT;
    for (int k = tid; k < FEAT * FEAT; k += 128) Ws[k] = wg[k];
    __syncthreads();

    const int jh    = tid >> 6;
    const int slot  = tid & 63;
    const int jbase = jh * 24;
    const int n0 = blockIdx.x * 128 + slot;
    const int n1 = n0 + 64;
    const bool v0 = (n0 < N_NODES);
    const bool v1 = (n1 < N_NODES);
    const int c0 = v0 ? n0 : 0;
    const int c1 = v1 ? n1 : 0;

    unsigned long long accA[12], accB[12];
#pragma unroll
    for (int k = 0; k < 12; k++) { accA[k] = 0ull; accB[k] = 0ull; }

    const float4* ha4 = reinterpret_cast<const float4*>(
        g_h1 + ((size_t)c0 * NUM_RELS + r) * FEAT);
    const float4* hb4 = reinterpret_cast<const float4*>(
        g_h1 + ((size_t)c1 * NUM_RELS + r) * FEAT);
#pragma unroll
    for (int i4 = 0; i4 < FEAT / 4; i4++) {
        float4 xa = ha4[i4];
        float4 xb = hb4[i4];
#pragma unroll
        for (int u = 0; u < 4; u++) {
            float ai = (u == 0) ? xa.x : (u == 1) ? xa.y : (u == 2) ? xa.z : xa.w;
            float bi = (u == 0) ? xb.x : (u == 1) ? xb.y : (u == 2) ? xb.z : xb.w;
            unsigned long long a2 = pack2(ai, ai);
            unsigned long long b2 = pack2(bi, bi);
            const ulonglong2* w = reinterpret_cast<const ulonglong2*>(
                Ws + (i4 * 4 + u) * FEAT + jbase);
#pragma unroll
            for (int k = 0; k < 6; k++) {
                ulonglong2 wv = w[k];
                FMA2(accA[2 * k],     a2, wv.x);
                FMA2(accA[2 * k + 1], a2, wv.y);
                FMA2(accB[2 * k],     b2, wv.x);
                FMA2(accB[2 * k + 1], b2, wv.y);
            }
        }
    }

    if (v0) {
        ulonglong2* orow = reinterpret_cast<ulonglong2*>(
            g_h2 + ((size_t)n0 * NUM_RELS + r) * FEAT + jbase);
#pragma unroll
        for (int k = 0; k < 6; k++) {
            ulonglong2 o; o.x = accA[2 * k]; o.y = accA[2 * k + 1];
            orow[k] = o;
        }
    }
    if (v1) {
        ulonglong2* orow = reinterpret_cast<ulonglong2*>(
            g_h2 + ((size_t)n1 * NUM_RELS + r) * FEAT + jbase);
#pragma unroll
        for (int k = 0; k < 6; k++) {
            ulonglong2 o; o.x = accB[2 * k]; o.y = accB[2 * k + 1];
            orow[k] = o;
        }
    }
}

// ---------------------------------------------------------------------------
// K6 (launch #6): scatter packed {h2 row offset, norm} into dst bins.
// ---------------------------------------------------------------------------
__global__ __launch_bounds__(256)
void scatter_kernel(const int* __restrict__ src,
                    const int* __restrict__ dst,
                    const int* __restrict__ rel,
                    const float* __restrict__ norm) {
    int e = blockIdx.x * 256 + threadIdx.x;
    if (e >= N_EDGES) return;
    const int is64 = g_src_is64;
    const int s  = is64 ? src[2 * e] : src[e];
    const int d  = dst[e];
    const int rl = rel[e];
    const float nm = norm[e];
    int pos = atomicAdd(&g_cur[d], 1);
    g_meta[pos] = make_int2((s * NUM_RELS + rl) * FEAT, __float_as_int(nm));
}

// ---------------------------------------------------------------------------
// K7 (launch #7): gather-side aggregation, no float atomics.
// ---------------------------------------------------------------------------
__global__ __launch_bounds__(192)
void agg_kernel(const float* __restrict__ b2, float* __restrict__ out) {
    const int t = threadIdx.x;
    const int d = blockIdx.x * 16 + t / 12;
    const int q = t % 12;
    if (d >= N_NODES) return;

    const int2*  __restrict__ meta = g_meta;
    const float* __restrict__ h2   = g_h2;

    int p  = g_off[d];
    const int pe = g_off[d + 1];

    float4 acc = make_float4(0.f, 0.f, 0.f, 0.f);

    for (; p + 3 < pe; p += 4) {
        int2 m0 = meta[p];
        int2 m1 = meta[p + 1];
        int2 m2 = meta[p + 2];
        int2 m3 = meta[p + 3];
        float4 v0 = reinterpret_cast<const float4*>(h2 + (size_t)m0.x)[q];
        float4 v1 = reinterpret_cast<const float4*>(h2 + (size_t)m1.x)[q];
        float4 v2 = reinterpret_cast<const float4*>(h2 + (size_t)m2.x)[q];
        float4 v3 = reinterpret_cast<const float4*>(h2 + (size_t)m3.x)[q];
        float n0 = __int_as_float(m0.y);
        float n1 = __int_as_float(m1.y);
        float n2 = __int_as_float(m2.y);
        float n3 = __int_as_float(m3.y);
        acc.x = fmaf(v0.x, n0, acc.x); acc.y = fmaf(v0.y, n0, acc.y);
        acc.z = fmaf(v0.z, n0, acc.z); acc.w = fmaf(v0.w, n0, acc.w);
        acc.x = fmaf(v1.x, n1, acc.x); acc.y = fmaf(v1.y, n1, acc.y);
        acc.z = fmaf(v1.z, n1, acc.z); acc.w = fmaf(v1.w, n1, acc.w);
        acc.x = fmaf(v2.x, n2, acc.x); acc.y = fmaf(v2.y, n2, acc.y);
        acc.z = fmaf(v2.z, n2, acc.z); acc.w = fmaf(v2.w, n2, acc.w);
        acc.x = fmaf(v3.x, n3, acc.x); acc.y = fmaf(v3.y, n3, acc.y);
        acc.z = fmaf(v3.z, n3, acc.z); acc.w = fmaf(v3.w, n3, acc.w);
    }
    for (; p < pe; p++) {
        int2 m0 = meta[p];
        float4 v0 = reinterpret_cast<const float4*>(h2 + (size_t)m0.x)[q];
        float n0 = __int_as_float(m0.y);
        acc.x = fmaf(v0.x, n0, acc.x); acc.y = fmaf(v0.y, n0, acc.y);
        acc.z = fmaf(v0.z, n0, acc.z); acc.w = fmaf(v0.w, n0, acc.w);
    }

    float4 bb = reinterpret_cast<const float4*>(b2)[q];
    float4 o;
    o.x = fmaxf(acc.x + bb.x, 0.0f);
    o.y = fmaxf(acc.y + bb.y, 0.0f);
    o.z = fmaxf(acc.z + bb.z, 0.0f);
    o.w = fmaxf(acc.w + bb.w, 0.0f);
    reinterpret_cast<float4*>(out + (size_t)d * FEAT)[q] = o;
}

// ---------------------------------------------------------------------------
// launch — stage1 is the 4th launch so ncu captures it.
// ---------------------------------------------------------------------------
extern "C" void kernel_launch(void* const* d_in, const int* in_sizes, int n_in,
                              void* d_out, int out_size) {
    const float* X    = (const float*)d_in[0];
    const float* norm = (const float*)d_in[1];
    const float* W1   = (const float*)d_in[2];
    const float* W2   = (const float*)d_in[3];
    const float* b1   = (const float*)d_in[4];
    const float* b2   = (const float*)d_in[5];
    const int*   src  = (const int*)d_in[6];   // int32 or int64 (detected)
    const int*   dst  = (const int*)d_in[7];
    const int*   rel  = (const int*)d_in[8];
    float* out = (float*)d_out;

    (void)in_sizes; (void)n_in; (void)out_size;

    // #1: zero counts + dtype detect
    zero_detect_kernel<<<(N_NODES + 255) / 256, 256>>>(src);
    // #2: dst histogram
    hist_kernel<<<(N_EDGES / 4 + 255) / 256, 256>>>((const int4*)dst);
    // #3: prefix scan
    scan_kernel<<<1, 1024>>>();

    // #4/#5: dense stages (stage1 PROFILED)
    dim3 gdense((N_NODES + 127) / 128, NUM_RELS);
    stage1_kernel<<<gdense, 128>>>(X, W1, b1);
    stage2_kernel<<<gdense, 128>>>(W2);

    // #6: bin edges by dst
    scatter_kernel<<<(N_EDGES + 255) / 256, 256>>>(src, dst, rel, norm);
    // #7: gather aggregation + bias + relu
    agg_kernel<<<(N_NODES + 15) / 16, 192>>>(b2, out);
}

// round 14
// speedup vs baseline: 1.2855x; 1.2855x over previous
#include <cuda_runtime.h>
#include <cuda_bf16.h>
#include <cstdint>

#define N_NODES 50000
#define N_EDGES 1600000
#define FEAT    48
#define NUM_RELS 8
#define XS_STRIDE 52   // 208 B row stride: 16B-aligned, conflict-free LDS.128 phases

// ---------------------------------------------------------------------------
// Scratch (__device__ globals — no allocations).
// ---------------------------------------------------------------------------
__device__ float g_h2[(size_t)N_NODES * NUM_RELS * FEAT];   // 76.8 MB
__device__ int   g_cnt[N_NODES];
__device__ int   g_off[N_NODES + 1];
__device__ int   g_cur[N_NODES];
__device__ int2  g_meta[N_EDGES];                            // 12.8 MB
__device__ int   g_src_is64;

// ---------------------------------------------------------------------------
// Packed f32x2 helpers (Blackwell) — only reachable via PTX.
// ---------------------------------------------------------------------------
__device__ __forceinline__ unsigned long long pack2(float lo, float hi) {
    unsigned long long r;
    asm("mov.b64 %0, {%1, %2};" : "=l"(r) : "f"(lo), "f"(hi));
    return r;
}
__device__ __forceinline__ void unpack2(float& lo, float& hi, unsigned long long v) {
    asm("mov.b64 {%0, %1}, %2;" : "=f"(lo), "=f"(hi) : "l"(v));
}
#define FMA2(d, a, b) \
    asm("fma.rn.f32x2 %0, %1, %2, %0;" : "+l"(d) : "l"(a), "l"(b))

// ---------------------------------------------------------------------------
// K1 (launch #1): zero counts + src dtype detection (block 0).
// ---------------------------------------------------------------------------
__global__ void zero_detect_kernel(const int* __restrict__ src) {
    int i = blockIdx.x * 256 + threadIdx.x;
    if (i < N_NODES) g_cnt[i] = 0;
    if (blockIdx.x == 0) {
        __shared__ int s_any;
        if (threadIdx.x == 0) s_any = 0;
        __syncthreads();
        unsigned v = (unsigned)src[2 * threadIdx.x + 1];
        unsigned any = __ballot_sync(0xFFFFFFFFu, v != 0u);
        if ((threadIdx.x & 31) == 0 && any) atomicOr(&s_any, 1);
        __syncthreads();
        if (threadIdx.x == 0) g_src_is64 = (s_any == 0) ? 1 : 0;
    }
}

// ---------------------------------------------------------------------------
// K2 (launch #2): dst histogram, int4-vectorized.
// ---------------------------------------------------------------------------
__global__ __launch_bounds__(256)
void hist_kernel(const int4* __restrict__ dst4) {
    int i = blockIdx.x * 256 + threadIdx.x;
    if (i < N_EDGES / 4) {
        int4 d = dst4[i];
        atomicAdd(&g_cnt[d.x], 1);
        atomicAdd(&g_cnt[d.y], 1);
        atomicAdd(&g_cnt[d.z], 1);
        atomicAdd(&g_cnt[d.w], 1);
    }
}

// ---------------------------------------------------------------------------
// K3 (launch #3): single-block exclusive scan g_cnt -> g_off, g_cur.
// ---------------------------------------------------------------------------
__global__ __launch_bounds__(1024)
void scan_kernel() {
    __shared__ int partial[1024];
    const int t = threadIdx.x;
    const int CH = (N_NODES + 1023) / 1024;  // 49
    const int base = t * CH;

    int s = 0;
    for (int i = 0; i < CH; i++) {
        int idx = base + i;
        if (idx < N_NODES) s += g_cnt[idx];
    }
    partial[t] = s;
    __syncthreads();
    for (int o = 1; o < 1024; o <<= 1) {
        int v = (t >= o) ? partial[t - o] : 0;
        __syncthreads();
        partial[t] += v;
        __syncthreads();
    }
    int run = (t == 0) ? 0 : partial[t - 1];
    for (int i = 0; i < CH; i++) {
        int idx = base + i;
        if (idx < N_NODES) {
            g_off[idx] = run;
            g_cur[idx] = run;
            run += g_cnt[idx];
        }
    }
    if (t == 1023) g_off[N_NODES] = partial[1023];
}

// ---------------------------------------------------------------------------
// K4 (launch #4 — PROFILED): fully fused dense stage, smem-staged.
//   h1 = relu(X @ W1[r] + b1); h2 = h1 @ W2[r]  -> g_h2[n][r][:]
// Block = 128 threads, 128 nodes, one relation.
//   Phase A: coalesced X tile load -> xs[node][52] (12 thr/row, ~2 lines/row)
//   Phase B: stage1 from smem (LDS.128, conflict-free; weights broadcast)
//   Phase C: h1 -> xs (smem exchange), W2 -> Ws
//   Phase D: stage2 from smem -> g_h2
// jh = tid>>6 (uniform per warp): output cols [jh*24, jh*24+24).
// slot = tid&63: nodes n0 = nb+slot, n1 = n0+64.
// 24 ull accumulators, ~80 regs, 36 KB smem -> ~5 blocks/SM (20 warps).
// ---------------------------------------------------------------------------
__global__ __launch_bounds__(128, 5)
void fused_gemm_kernel(const float* __restrict__ X,
                       const float* __restrict__ W1,
                       const float* __restrict__ W2,
                       const float* __restrict__ b1) {
    __shared__ __align__(16) float xs[128 * XS_STRIDE];  // X tile, then h1 tile
    __shared__ __align__(16) float Ws[FEAT * FEAT];      // W1, then W2
    __shared__ float bs[FEAT];

    const int r   = blockIdx.y;
    const int tid = threadIdx.x;
    const int nb  = blockIdx.x * 128;

    // ---- Phase A: W1 + b1 + coalesced X tile ----
    {
        const float* wg = W1 + (size_t)r * FEAT * FEAT;
        for (int k = tid; k < FEAT * FEAT; k += 128) Ws[k] = wg[k];
        if (tid < FEAT) bs[tid] = b1[tid];
#pragma unroll
        for (int i = 0; i < 12; i++) {
            int f   = i * 128 + tid;       // 0..1535
            int row = f / 12;              // node within tile
            int c4  = f % 12;              // float4 column
            int node = nb + row;
            if (node < N_NODES) {
                float4 v = reinterpret_cast<const float4*>(
                    X + (size_t)node * FEAT)[c4];
                reinterpret_cast<float4*>(xs + row * XS_STRIDE)[c4] = v;
            }
        }
    }
    __syncthreads();

    const int jh    = tid >> 6;
    const int slot  = tid & 63;
    const int jbase = jh * 24;
    const int n0 = nb + slot;
    const int n1 = n0 + 64;
    const bool v0 = (n0 < N_NODES);
    const bool v1 = (n1 < N_NODES);

    const float4* xa4 = reinterpret_cast<const float4*>(xs + slot * XS_STRIDE);
    const float4* xb4 = reinterpret_cast<const float4*>(xs + (slot + 64) * XS_STRIDE);

    // ---- Phase B: stage 1 ----
    unsigned long long accA[12], accB[12];
#pragma unroll
    for (int k = 0; k < 12; k++) {
        unsigned long long b = pack2(bs[jbase + 2 * k], bs[jbase + 2 * k + 1]);
        accA[k] = b;
        accB[k] = b;
    }

#pragma unroll
    for (int i4 = 0; i4 < FEAT / 4; i4++) {
        float4 xa = xa4[i4];
        float4 xb = xb4[i4];
#pragma unroll
        for (int u = 0; u < 4; u++) {
            float ai = (u == 0) ? xa.x : (u == 1) ? xa.y : (u == 2) ? xa.z : xa.w;
            float bi = (u == 0) ? xb.x : (u == 1) ? xb.y : (u == 2) ? xb.z : xb.w;
            unsigned long long a2 = pack2(ai, ai);
            unsigned long long b2 = pack2(bi, bi);
            const ulonglong2* w = reinterpret_cast<const ulonglong2*>(
                Ws + (i4 * 4 + u) * FEAT + jbase);
#pragma unroll
            for (int k = 0; k < 6; k++) {
                ulonglong2 wv = w[k];
                FMA2(accA[2 * k],     a2, wv.x);
                FMA2(accA[2 * k + 1], a2, wv.y);
                FMA2(accB[2 * k],     b2, wv.x);
                FMA2(accB[2 * k + 1], b2, wv.y);
            }
        }
    }
    __syncthreads();   // all stage-1 reads of xs & Ws complete

    // ---- Phase C: relu(h1) -> xs, W2 -> Ws ----
    {
        float4* ha = reinterpret_cast<float4*>(xs + slot * XS_STRIDE + jbase);
        float4* hb = reinterpret_cast<float4*>(xs + (slot + 64) * XS_STRIDE + jbase);
#pragma unroll
        for (int k = 0; k < 6; k++) {
            float x0, x1, x2, x3;
            unpack2(x0, x1, accA[2 * k]);
            unpack2(x2, x3, accA[2 * k + 1]);
            ha[k] = make_float4(fmaxf(x0, 0.f), fmaxf(x1, 0.f),
                                fmaxf(x2, 0.f), fmaxf(x3, 0.f));
            unpack2(x0, x1, accB[2 * k]);
            unpack2(x2, x3, accB[2 * k + 1]);
            hb[k] = make_float4(fmaxf(x0, 0.f), fmaxf(x1, 0.f),
                                fmaxf(x2, 0.f), fmaxf(x3, 0.f));
        }
        const float* wg = W2 + (size_t)r * FEAT * FEAT;
        for (int k = tid; k < FEAT * FEAT; k += 128) Ws[k] = wg[k];
    }
    __syncthreads();

    // ---- Phase D: stage 2 ----
#pragma unroll
    for (int k = 0; k < 12; k++) { accA[k] = 0ull; accB[k] = 0ull; }

#pragma unroll
    for (int i4 = 0; i4 < FEAT / 4; i4++) {
        float4 xa = xa4[i4];
        float4 xb = xb4[i4];
#pragma unroll
        for (int u = 0; u < 4; u++) {
            float ai = (u == 0) ? xa.x : (u == 1) ? xa.y : (u == 2) ? xa.z : xa.w;
            float bi = (u == 0) ? xb.x : (u == 1) ? xb.y : (u == 2) ? xb.z : xb.w;
            unsigned long long a2 = pack2(ai, ai);
            unsigned long long b2 = pack2(bi, bi);
            const ulonglong2* w = reinterpret_cast<const ulonglong2*>(
                Ws + (i4 * 4 + u) * FEAT + jbase);
#pragma unroll
            for (int k = 0; k < 6; k++) {
                ulonglong2 wv = w[k];
                FMA2(accA[2 * k],     a2, wv.x);
                FMA2(accA[2 * k + 1], a2, wv.y);
                FMA2(accB[2 * k],     b2, wv.x);
                FMA2(accB[2 * k + 1], b2, wv.y);
            }
        }
    }

    if (v0) {
        ulonglong2* orow = reinterpret_cast<ulonglong2*>(
            g_h2 + ((size_t)n0 * NUM_RELS + r) * FEAT + jbase);
#pragma unroll
        for (int k = 0; k < 6; k++) {
            ulonglong2 o; o.x = accA[2 * k]; o.y = accA[2 * k + 1];
            orow[k] = o;
        }
    }
    if (v1) {
        ulonglong2* orow = reinterpret_cast<ulonglong2*>(
            g_h2 + ((size_t)n1 * NUM_RELS + r) * FEAT + jbase);
#pragma unroll
        for (int k = 0; k < 6; k++) {
            ulonglong2 o; o.x = accB[2 * k]; o.y = accB[2 * k + 1];
            orow[k] = o;
        }
    }
}

// ---------------------------------------------------------------------------
// K5 (launch #5): scatter packed {h2 row offset, norm} into dst bins.
// ---------------------------------------------------------------------------
__global__ __launch_bounds__(256)
void scatter_kernel(const int* __restrict__ src,
                    const int* __restrict__ dst,
                    const int* __restrict__ rel,
                    const float* __restrict__ norm) {
    int e = blockIdx.x * 256 + threadIdx.x;
    if (e >= N_EDGES) return;
    const int is64 = g_src_is64;
    const int s  = is64 ? src[2 * e] : src[e];
    const int d  = dst[e];
    const int rl = rel[e];
    const float nm = norm[e];
    int pos = atomicAdd(&g_cur[d], 1);
    g_meta[pos] = make_int2((s * NUM_RELS + rl) * FEAT, __float_as_int(nm));
}

// ---------------------------------------------------------------------------
// K6 (launch #6): gather-side aggregation, no float atomics.
// 12 threads per dst (one float4 quad each); bias2 + relu at writeback.
// ---------------------------------------------------------------------------
__global__ __launch_bounds__(192)
void agg_kernel(const float* __restrict__ b2, float* __restrict__ out) {
    const int t = threadIdx.x;
    const int d = blockIdx.x * 16 + t / 12;
    const int q = t % 12;
    if (d >= N_NODES) return;

    const int2*  __restrict__ meta = g_meta;
    const float* __restrict__ h2   = g_h2;

    int p  = g_off[d];
    const int pe = g_off[d + 1];

    float4 acc = make_float4(0.f, 0.f, 0.f, 0.f);

    for (; p + 3 < pe; p += 4) {
        int2 m0 = meta[p];
        int2 m1 = meta[p + 1];
        int2 m2 = meta[p + 2];
        int2 m3 = meta[p + 3];
        float4 v0 = reinterpret_cast<const float4*>(h2 + (size_t)m0.x)[q];
        float4 v1 = reinterpret_cast<const float4*>(h2 + (size_t)m1.x)[q];
        float4 v2 = reinterpret_cast<const float4*>(h2 + (size_t)m2.x)[q];
        float4 v3 = reinterpret_cast<const float4*>(h2 + (size_t)m3.x)[q];
        float n0 = __int_as_float(m0.y);
        float n1 = __int_as_float(m1.y);
        float n2 = __int_as_float(m2.y);
        float n3 = __int_as_float(m3.y);
        acc.x = fmaf(v0.x, n0, acc.x); acc.y = fmaf(v0.y, n0, acc.y);
        acc.z = fmaf(v0.z, n0, acc.z); acc.w = fmaf(v0.w, n0, acc.w);
        acc.x = fmaf(v1.x, n1, acc.x); acc.y = fmaf(v1.y, n1, acc.y);
        acc.z = fmaf(v1.z, n1, acc.z); acc.w = fmaf(v1.w, n1, acc.w);
        acc.x = fmaf(v2.x, n2, acc.x); acc.y = fmaf(v2.y, n2, acc.y);
        acc.z = fmaf(v2.z, n2, acc.z); acc.w = fmaf(v2.w, n2, acc.w);
        acc.x = fmaf(v3.x, n3, acc.x); acc.y = fmaf(v3.y, n3, acc.y);
        acc.z = fmaf(v3.z, n3, acc.z); acc.w = fmaf(v3.w, n3, acc.w);
    }
    for (; p < pe; p++) {
        int2 m0 = meta[p];
        float4 v0 = reinterpret_cast<const float4*>(h2 + (size_t)m0.x)[q];
        float n0 = __int_as_float(m0.y);
        acc.x = fmaf(v0.x, n0, acc.x); acc.y = fmaf(v0.y, n0, acc.y);
        acc.z = fmaf(v0.z, n0, acc.z); acc.w = fmaf(v0.w, n0, acc.w);
    }

    float4 bb = reinterpret_cast<const float4*>(b2)[q];
    float4 o;
    o.x = fmaxf(acc.x + bb.x, 0.0f);
    o.y = fmaxf(acc.y + bb.y, 0.0f);
    o.z = fmaxf(acc.z + bb.z, 0.0f);
    o.w = fmaxf(acc.w + bb.w, 0.0f);
    reinterpret_cast<float4*>(out + (size_t)d * FEAT)[q] = o;
}

// ---------------------------------------------------------------------------
// launch — fused gemm is the 4th launch so ncu captures it.
// ---------------------------------------------------------------------------
extern "C" void kernel_launch(void* const* d_in, const int* in_sizes, int n_in,
                              void* d_out, int out_size) {
    const float* X    = (const float*)d_in[0];
    const float* norm = (const float*)d_in[1];
    const float* W1   = (const float*)d_in[2];
    const float* W2   = (const float*)d_in[3];
    const float* b1   = (const float*)d_in[4];
    const float* b2   = (const float*)d_in[5];
    const int*   src  = (const int*)d_in[6];   // int32 or int64 (detected)
    const int*   dst  = (const int*)d_in[7];
    const int*   rel  = (const int*)d_in[8];
    float* out = (float*)d_out;

    (void)in_sizes; (void)n_in; (void)out_size;

    // #1: zero counts + dtype detect
    zero_detect_kernel<<<(N_NODES + 255) / 256, 256>>>(src);
    // #2: dst histogram
    hist_kernel<<<(N_EDGES / 4 + 255) / 256, 256>>>((const int4*)dst);
    // #3: prefix scan
    scan_kernel<<<1, 1024>>>();

    // #4: fused dense stage (PROFILED)
    dim3 gdense((N_NODES + 127) / 128, NUM_RELS);
    fused_gemm_kernel<<<gdense, 128>>>(X, W1, W2, b1);

    // #5: bin edges by dst
    scatter_kernel<<<(N_EDGES + 255) / 256, 256>>>(src, dst, rel, norm);
    // #6: gather aggregation + bias + relu
    agg_kernel<<<(N_NODES + 15) / 16, 192>>>(b2, out);
}

// round 17
// speedup vs baseline: 1.3120x; 1.0206x over previous
#include <cuda_runtime.h>
#include <cuda_bf16.h>
#include <cstdint>

#define N_NODES 50000
#define N_EDGES 1600000
#define FEAT    48
#define NUM_RELS 8
#define XS_STRIDE 52   // 208 B row stride: 16B-aligned, conflict-free LDS.128 phases

// ---------------------------------------------------------------------------
// Scratch (__device__ globals — no allocations).
// ---------------------------------------------------------------------------
__device__ float g_h2[(size_t)N_NODES * NUM_RELS * FEAT];   // 76.8 MB
__device__ int   g_cnt[N_NODES];
__device__ int   g_off[N_NODES + 1];
__device__ int   g_cur[N_NODES];
__device__ int2  g_meta[N_EDGES];                            // 12.8 MB
__device__ int   g_src_is64;

// ---------------------------------------------------------------------------
// Packed f32x2 helpers (Blackwell) — only reachable via PTX.
// ---------------------------------------------------------------------------
__device__ __forceinline__ unsigned long long pack2(float lo, float hi) {
    unsigned long long r;
    asm("mov.b64 %0, {%1, %2};" : "=l"(r) : "f"(lo), "f"(hi));
    return r;
}
__device__ __forceinline__ void unpack2(float& lo, float& hi, unsigned long long v) {
    asm("mov.b64 {%0, %1}, %2;" : "=f"(lo), "=f"(hi) : "l"(v));
}
#define FMA2(d, a, b) \
    asm("fma.rn.f32x2 %0, %1, %2, %0;" : "+l"(d) : "l"(a), "l"(b))

// ---------------------------------------------------------------------------
// K1 (launch #1): zero counts + src dtype detection (block 0).
// ---------------------------------------------------------------------------
__global__ void zero_detect_kernel(const int* __restrict__ src) {
    int i = blockIdx.x * 256 + threadIdx.x;
    if (i < N_NODES) g_cnt[i] = 0;
    if (blockIdx.x == 0) {
        __shared__ int s_any;
        if (threadIdx.x == 0) s_any = 0;
        __syncthreads();
        unsigned v = (unsigned)src[2 * threadIdx.x + 1];
        unsigned any = __ballot_sync(0xFFFFFFFFu, v != 0u);
        if ((threadIdx.x & 31) == 0 && any) atomicOr(&s_any, 1);
        __syncthreads();
        if (threadIdx.x == 0) g_src_is64 = (s_any == 0) ? 1 : 0;
    }
}

// ---------------------------------------------------------------------------
// K2 (launch #2): dst histogram, int4-vectorized.
// ---------------------------------------------------------------------------
__global__ __launch_bounds__(256)
void hist_kernel(const int4* __restrict__ dst4) {
    int i = blockIdx.x * 256 + threadIdx.x;
    if (i < N_EDGES / 4) {
        int4 d = dst4[i];
        atomicAdd(&g_cnt[d.x], 1);
        atomicAdd(&g_cnt[d.y], 1);
        atomicAdd(&g_cnt[d.z], 1);
        atomicAdd(&g_cnt[d.w], 1);
    }
}

// ---------------------------------------------------------------------------
// K3 (launch #3): single-block exclusive scan g_cnt -> g_off, g_cur.
// ---------------------------------------------------------------------------
__global__ __launch_bounds__(1024)
void scan_kernel() {
    __shared__ int partial[1024];
    const int t = threadIdx.x;
    const int CH = (N_NODES + 1023) / 1024;  // 49
    const int base = t * CH;

    int s = 0;
    for (int i = 0; i < CH; i++) {
        int idx = base + i;
        if (idx < N_NODES) s += g_cnt[idx];
    }
    partial[t] = s;
    __syncthreads();
    for (int o = 1; o < 1024; o <<= 1) {
        int v = (t >= o) ? partial[t - o] : 0;
        __syncthreads();
        partial[t] += v;
        __syncthreads();
    }
    int run = (t == 0) ? 0 : partial[t - 1];
    for (int i = 0; i < CH; i++) {
        int idx = base + i;
        if (idx < N_NODES) {
            g_off[idx] = run;
            g_cur[idx] = run;
            run += g_cnt[idx];
        }
    }
    if (t == 1023) g_off[N_NODES] = partial[1023];
}

// ---------------------------------------------------------------------------
// K4 (launch #4 — PROFILED): fused dense stage, retiled T=4 nodes/thread,
// J=12 outputs/thread.
//   warp w owns output cols [12w, 12w+12)  (uniform per warp -> broadcast LDS)
//   lane l owns nodes nb + l + {0,32,64,96}
// Per u-step: 3 weight LDS.128 feed 24 FMA2  ->  FMA2:LDS = 8:1 (was 4:1).
// Accs: 4 nodes x 6 f32x2 = 24 ull = 48 regs; total ~90 regs.
// ---------------------------------------------------------------------------
__global__ __launch_bounds__(128, 5)
void fused_gemm_kernel(const float* __restrict__ X,
                       const float* __restrict__ W1,
                       const float* __restrict__ W2,
                       const float* __restrict__ b1) {
    __shared__ __align__(16) float xs[128 * XS_STRIDE];  // X tile, then h1 tile
    __shared__ __align__(16) float Ws[FEAT * FEAT];      // W1, then W2
    __shared__ float bs[FEAT];

    const int r   = blockIdx.y;
    const int tid = threadIdx.x;
    const int nb  = blockIdx.x * 128;

    // ---- Phase A: W1 + b1 + coalesced X tile ----
    {
        const float* wg = W1 + (size_t)r * FEAT * FEAT;
        for (int k = tid; k < FEAT * FEAT; k += 128) Ws[k] = wg[k];
        if (tid < FEAT) bs[tid] = b1[tid];
#pragma unroll
        for (int i = 0; i < 12; i++) {
            int f   = i * 128 + tid;       // 0..1535
            int row = f / 12;              // node within tile
            int c4  = f % 12;              // float4 column
            int node = nb + row;
            if (node < N_NODES) {
                float4 v = reinterpret_cast<const float4*>(
                    X + (size_t)node * FEAT)[c4];
                reinterpret_cast<float4*>(xs + row * XS_STRIDE)[c4] = v;
            }
        }
    }
    __syncthreads();

    const int wid   = tid >> 5;
    const int lane  = tid & 31;
    const int jbase = wid * 12;

    // ---- Phase B: stage 1, h1 = relu(X @ W1 + b1) ----
    unsigned long long acc[4][6];
#pragma unroll
    for (int i = 0; i < 4; i++)
#pragma unroll
        for (int m = 0; m < 6; m++)
            acc[i][m] = pack2(bs[jbase + 2 * m], bs[jbase + 2 * m + 1]);

#pragma unroll
    for (int i4 = 0; i4 < FEAT / 4; i4++) {
        float4 xv[4];
#pragma unroll
        for (int i = 0; i < 4; i++)
            xv[i] = *reinterpret_cast<const float4*>(
                xs + (lane + 32 * i) * XS_STRIDE + i4 * 4);
#pragma unroll
        for (int u = 0; u < 4; u++) {
            const ulonglong2* w = reinterpret_cast<const ulonglong2*>(
                Ws + (i4 * 4 + u) * FEAT + jbase);
            ulonglong2 w0 = w[0];
            ulonglong2 w1 = w[1];
            ulonglong2 w2 = w[2];
#pragma unroll
            for (int i = 0; i < 4; i++) {
                float xi = (u == 0) ? xv[i].x : (u == 1) ? xv[i].y
                         : (u == 2) ? xv[i].z : xv[i].w;
                unsigned long long x2 = pack2(xi, xi);
                FMA2(acc[i][0], x2, w0.x);
                FMA2(acc[i][1], x2, w0.y);
                FMA2(acc[i][2], x2, w1.x);
                FMA2(acc[i][3], x2, w1.y);
                FMA2(acc[i][4], x2, w2.x);
                FMA2(acc[i][5], x2, w2.y);
            }
        }
    }
    __syncthreads();   // stage-1 reads of xs & Ws complete

    // ---- Phase C: relu(h1) -> xs (cols jbase..jbase+12), W2 -> Ws ----
#pragma unroll
    for (int i = 0; i < 4; i++) {
        float4* h = reinterpret_cast<float4*>(
            xs + (lane + 32 * i) * XS_STRIDE + jbase);
#pragma unroll
        for (int m = 0; m < 3; m++) {
            float x0, x1, x2, x3;
            unpack2(x0, x1, acc[i][2 * m]);
            unpack2(x2, x3, acc[i][2 * m + 1]);
            h[m] = make_float4(fmaxf(x0, 0.f), fmaxf(x1, 0.f),
                               fmaxf(x2, 0.f), fmaxf(x3, 0.f));
        }
    }
    {
        const float* wg = W2 + (size_t)r * FEAT * FEAT;
        for (int k = tid; k < FEAT * FEAT; k += 128) Ws[k] = wg[k];
    }
    __syncthreads();

    // ---- Phase D: stage 2, h2 = h1 @ W2 ----
#pragma unroll
    for (int i = 0; i < 4; i++)
#pragma unroll
        for (int m = 0; m < 6; m++)
            acc[i][m] = 0ull;

#pragma unroll
    for (int i4 = 0; i4 < FEAT / 4; i4++) {
        float4 xv[4];
#pragma unroll
        for (int i = 0; i < 4; i++)
            xv[i] = *reinterpret_cast<const float4*>(
                xs + (lane + 32 * i) * XS_STRIDE + i4 * 4);
#pragma unroll
        for (int u = 0; u < 4; u++) {
            const ulonglong2* w = reinterpret_cast<const ulonglong2*>(
                Ws + (i4 * 4 + u) * FEAT + jbase);
            ulonglong2 w0 = w[0];
            ulonglong2 w1 = w[1];
            ulonglong2 w2 = w[2];
#pragma unroll
            for (int i = 0; i < 4; i++) {
                float xi = (u == 0) ? xv[i].x : (u == 1) ? xv[i].y
                         : (u == 2) ? xv[i].z : xv[i].w;
                unsigned long long x2 = pack2(xi, xi);
                FMA2(acc[i][0], x2, w0.x);
                FMA2(acc[i][1], x2, w0.y);
                FMA2(acc[i][2], x2, w1.x);
                FMA2(acc[i][3], x2, w1.y);
                FMA2(acc[i][4], x2, w2.x);
                FMA2(acc[i][5], x2, w2.y);
            }
        }
    }

    // ---- store h2 (12 floats per node, 3 x 16B STG) ----
#pragma unroll
    for (int i = 0; i < 4; i++) {
        int n = nb + lane + 32 * i;
        if (n < N_NODES) {
            ulonglong2* orow = reinterpret_cast<ulonglong2*>(
                g_h2 + ((size_t)n * NUM_RELS + r) * FEAT + jbase);
#pragma unroll
            for (int m = 0; m < 3; m++) {
                ulonglong2 o;
                o.x = acc[i][2 * m];
                o.y = acc[i][2 * m + 1];
                orow[m] = o;
            }
        }
    }
}

// ---------------------------------------------------------------------------
// K5 (launch #5): scatter packed {h2 row offset, norm} into dst bins.
// ---------------------------------------------------------------------------
__global__ __launch_bounds__(256)
void scatter_kernel(const int* __restrict__ src,
                    const int* __restrict__ dst,
                    const int* __restrict__ rel,
                    const float* __restrict__ norm) {
    int e = blockIdx.x * 256 + threadIdx.x;
    if (e >= N_EDGES) return;
    const int is64 = g_src_is64;
    const int s  = is64 ? src[2 * e] : src[e];
    const int d  = dst[e];
    const int rl = rel[e];
    const float nm = norm[e];
    int pos = atomicAdd(&g_cur[d], 1);
    g_meta[pos] = make_int2((s * NUM_RELS + rl) * FEAT, __float_as_int(nm));
}

// ---------------------------------------------------------------------------
// K6 (launch #6): gather-side aggregation, no float atomics.
// 12 threads per dst (one float4 quad each); 8-way unroll for MLP≈8;
// bias2 + relu at writeback.
// ---------------------------------------------------------------------------
__global__ __launch_bounds__(192)
void agg_kernel(const float* __restrict__ b2, float* __restrict__ out) {
    const int t = threadIdx.x;
    const int d = blockIdx.x * 16 + t / 12;
    const int q = t % 12;
    if (d >= N_NODES) return;

    const int2*  __restrict__ meta = g_meta;
    const float* __restrict__ h2   = g_h2;

    int p  = g_off[d];
    const int pe = g_off[d + 1];

    float4 acc = make_float4(0.f, 0.f, 0.f, 0.f);

    for (; p + 7 < pe; p += 8) {
        int2   m[8];
        float4 v[8];
#pragma unroll
        for (int u = 0; u < 8; u++) m[u] = meta[p + u];
#pragma unroll
        for (int u = 0; u < 8; u++)
            v[u] = reinterpret_cast<const float4*>(h2 + (size_t)m[u].x)[q];
#pragma unroll
        for (int u = 0; u < 8; u++) {
            float nn = __int_as_float(m[u].y);
            acc.x = fmaf(v[u].x, nn, acc.x);
            acc.y = fmaf(v[u].y, nn, acc.y);
            acc.z = fmaf(v[u].z, nn, acc.z);
            acc.w = fmaf(v[u].w, nn, acc.w);
        }
    }
    for (; p < pe; p++) {
        int2 m0 = meta[p];
        float4 v0 = reinterpret_cast<const float4*>(h2 + (size_t)m0.x)[q];
        float n0 = __int_as_float(m0.y);
        acc.x = fmaf(v0.x, n0, acc.x);
        acc.y = fmaf(v0.y, n0, acc.y);
        acc.z = fmaf(v0.z, n0, acc.z);
        acc.w = fmaf(v0.w, n0, acc.w);
    }

    float4 bb = reinterpret_cast<const float4*>(b2)[q];
    float4 o;
    o.x = fmaxf(acc.x + bb.x, 0.0f);
    o.y = fmaxf(acc.y + bb.y, 0.0f);
    o.z = fmaxf(acc.z + bb.z, 0.0f);
    o.w = fmaxf(acc.w + bb.w, 0.0f);
    reinterpret_cast<float4*>(out + (size_t)d * FEAT)[q] = o;
}

// ---------------------------------------------------------------------------
// launch — fused gemm is the 4th launch so ncu captures it.
// ---------------------------------------------------------------------------
extern "C" void kernel_launch(void* const* d_in, const int* in_sizes, int n_in,
                              void* d_out, int out_size) {
    const float* X    = (const float*)d_in[0];
    const float* norm = (const float*)d_in[1];
    const float* W1   = (const float*)d_in[2];
    const float* W2   = (const float*)d_in[3];
    const float* b1   = (const float*)d_in[4];
    const float* b2   = (const float*)d_in[5];
    const int*   src  = (const int*)d_in[6];   // int32 or int64 (detected)
    const int*   dst  = (const int*)d_in[7];
    const int*   rel  = (const int*)d_in[8];
    float* out = (float*)d_out;

    (void)in_sizes; (void)n_in; (void)out_size;

    // #1: zero counts + dtype detect
    zero_detect_kernel<<<(N_NODES + 255) / 256, 256>>>(src);
    // #2: dst histogram
    hist_kernel<<<(N_EDGES / 4 + 255) / 256, 256>>>((const int4*)dst);
    // #3: prefix scan
    scan_kernel<<<1, 1024>>>();

    // #4: fused dense stage (PROFILED)
    dim3 gdense((N_NODES + 127) / 128, NUM_RELS);
    fused_gemm_kernel<<<gdense, 128>>>(X, W1, W2, b1);

    // #5: bin edges by dst
    scatter_kernel<<<(N_EDGES + 255) / 256, 256>>>(src, dst, rel, norm);
    // #6: gather aggregation + bias + relu
    agg_kernel<<<(N_NODES + 15) / 16, 192>>>(b2, out);
}